// round 4
// baseline (speedup 1.0000x reference)
#include <cuda_runtime.h>
#include <cuda_bf16.h>

// ROI mean-pool, v4: float4 stage-in + in-place column scan +
// WARP-per-box evaluation with lane-parallel column sums.
//
// fmap:  [B=64, C=256, H=80, W=80] float32
// boxes: [B=64, N=100, 4] xyxy in [0,640]
// out:   [B, N, C] float32

#define Bn   64
#define Cn   256
#define Hn   80
#define Wn   80
#define Nn   100

__global__ __launch_bounds__(256, 1)
void roi_pool_v4_kernel(const float* __restrict__ fmap,
                        const float* __restrict__ boxes,
                        float* __restrict__ out)
{
    // [0 .. 6399]   : plane -> (in-place) inclusive column prefix, rows 1..80
    // [6400 .. 6479]: zero row (acts as C[0])
    __shared__ float S[Hn * Wn + Wn];          // 25,920 B
    __shared__ int4  BC[Nn];                   // precomputed clipped box coords

    const int p    = blockIdx.x;               // plane id = b*Cn + c
    const int b    = p >> 8;
    const int c    = p & 255;
    const int tid  = threadIdx.x;
    const int wid  = tid >> 5;
    const int lane = tid & 31;

    const float* __restrict__ plane = fmap + (size_t)p * (Hn * Wn);

    // Phase 1a: coalesced float4 stage-in with all 256 threads (high MLP).
    #pragma unroll
    for (int i = tid; i < (Hn * Wn) / 4; i += 256) {
        float4 v = reinterpret_cast<const float4*>(plane)[i];
        reinterpret_cast<float4*>(S)[i] = v;
    }
    if (tid < Wn) S[Hn * Wn + tid] = 0.0f;     // zero border row

    // Phase 1b (overlapped): threads 0..99 precompute box coords once.
    if (tid < Nn) {
        float4 bb = reinterpret_cast<const float4*>(boxes + (size_t)b * (Nn * 4))[tid];
        // Match JAX exactly: IEEE div by 640, IEEE mul by 80, trunc, clip.
        int x1 = min(max((int)(__fmul_rn(__fdiv_rn(bb.x, 640.0f), 80.0f)), 0), Wn);
        int y1 = min(max((int)(__fmul_rn(__fdiv_rn(bb.y, 640.0f), 80.0f)), 0), Hn);
        int x2 = min(max((int)(__fmul_rn(__fdiv_rn(bb.z, 640.0f), 80.0f)), 0), Wn);
        int y2 = min(max((int)(__fmul_rn(__fdiv_rn(bb.w, 640.0f), 80.0f)), 0), Hn);
        BC[tid] = make_int4(x1, y1, x2, y2);
    }
    __syncthreads();

    // Phase 2: in-place inclusive column scan (thread x owns column x).
    if (tid < Wn) {
        float acc = 0.0f;
        #pragma unroll 8
        for (int y = 0; y < Hn; ++y) {
            acc += S[y * Wn + tid];
            S[y * Wn + tid] = acc;             // S[y*Wn+x] = C[y+1][x]
        }
    }
    __syncthreads();

    // Phase 3: warp-per-box. Lanes cover columns x1+lane, +32, +64 (conflict-free),
    // then shuffle-reduce. All 8 warps participate.
    float* __restrict__ ob = out + (size_t)b * (Nn * Cn) + c;
    const float* __restrict__ zrow = &S[Hn * Wn];

    for (int n = wid; n < Nn; n += 8) {
        int4 q = BC[n];
        const float* __restrict__ r2 = (q.w > 0) ? &S[(q.w - 1) * Wn] : zrow;
        const float* __restrict__ r1 = (q.y > 0) ? &S[(q.y - 1) * Wn] : zrow;

        float s = 0.0f;
        for (int x = q.x + lane; x < q.z; x += 32)
            s += r2[x] - r1[x];                // consecutive lanes -> 1 wavefront

        #pragma unroll
        for (int o = 16; o > 0; o >>= 1)
            s += __shfl_down_sync(0xFFFFFFFFu, s, o);

        if (lane == 0) {
            int dy = q.w - q.y;
            int dx = q.z - q.x;
            bool valid = (dy > 0) && (dx > 0);
            int  area  = max(dy * dx, 1);
            ob[(size_t)n * Cn] = valid ? s / (float)area : 0.0f;
        }
    }
}

extern "C" void kernel_launch(void* const* d_in, const int* in_sizes, int n_in,
                              void* d_out, int out_size)
{
    const float* fmap  = (const float*)d_in[0];   // [64,256,80,80]
    const float* boxes = (const float*)d_in[1];   // [64,100,4]
    float*       out   = (float*)d_out;           // [64,100,256]

    (void)in_sizes; (void)n_in; (void)out_size;

    roi_pool_v4_kernel<<<Bn * Cn, 256>>>(fmap, boxes, out);
}

// round 5
// speedup vs baseline: 2.5716x; 2.5716x over previous
#include <cuda_runtime.h>
#include <cuda_bf16.h>

// ROI mean-pool, v5: float4 stage-in + in-place column scan +
// 8-lane-TEAM-per-box evaluation (conflict-light LDS, cheap width-8 reduce).
//
// fmap:  [B=64, C=256, H=80, W=80] float32
// boxes: [B=64, N=100, 4] xyxy in [0,640]
// out:   [B, N, C] float32

#define Bn   64
#define Cn   256
#define Hn   80
#define Wn   80
#define Nn   100

__global__ __launch_bounds__(256, 1)
void roi_pool_v5_kernel(const float* __restrict__ fmap,
                        const float* __restrict__ boxes,
                        float* __restrict__ out)
{
    // [0 .. 6399]   : plane -> (in-place) inclusive column prefix, rows 1..80
    // [6400 .. 6479]: zero row (acts as C[0])
    __shared__ __align__(16) float S[Hn * Wn + Wn];   // 25,920 B
    __shared__ int4 BC[Nn];                            // clipped box coords

    const int p    = blockIdx.x;               // plane id = b*Cn + c
    const int b    = p >> 8;
    const int c    = p & 255;
    const int tid  = threadIdx.x;

    const float* __restrict__ plane = fmap + (size_t)p * (Hn * Wn);

    // Phase 1a: coalesced float4 stage-in with all 256 threads (high MLP).
    #pragma unroll
    for (int i = tid; i < (Hn * Wn) / 4; i += 256) {
        float4 v = reinterpret_cast<const float4*>(plane)[i];
        reinterpret_cast<float4*>(S)[i] = v;
    }
    if (tid < Wn) S[Hn * Wn + tid] = 0.0f;     // zero border row

    // Phase 1b (overlapped): threads 0..99 precompute box coords once.
    if (tid < Nn) {
        float4 bb = reinterpret_cast<const float4*>(boxes + (size_t)b * (Nn * 4))[tid];
        // Match JAX exactly: IEEE div by 640, IEEE mul by 80, trunc, clip.
        int x1 = min(max((int)(__fmul_rn(__fdiv_rn(bb.x, 640.0f), 80.0f)), 0), Wn);
        int y1 = min(max((int)(__fmul_rn(__fdiv_rn(bb.y, 640.0f), 80.0f)), 0), Hn);
        int x2 = min(max((int)(__fmul_rn(__fdiv_rn(bb.z, 640.0f), 80.0f)), 0), Wn);
        int y2 = min(max((int)(__fmul_rn(__fdiv_rn(bb.w, 640.0f), 80.0f)), 0), Hn);
        BC[tid] = make_int4(x1, y1, x2, y2);
    }
    __syncthreads();

    // Phase 2: in-place inclusive column scan (thread x owns column x).
    // 80 consecutive lanes hit 80 consecutive words per iteration: conflict-free.
    if (tid < Wn) {
        float acc = 0.0f;
        #pragma unroll 8
        for (int y = 0; y < Hn; ++y) {
            acc += S[y * Wn + tid];
            S[y * Wn + tid] = acc;             // S[y*Wn+x] = C[y+1][x]
        }
    }
    __syncthreads();

    // Phase 3: 8-lane team per box. 32 teams -> all warps busy, 3-4 boxes each.
    // Lanes cover x1+tl, x1+tl+8, ... : consecutive-address runs, few conflicts.
    // N=100 is divisible by 4, so all 4 teams of a warp always share the same
    // loop-iteration validity -> full-warp shuffles are safe.
    const int team = tid >> 3;                 // 0..31
    const int tl   = tid & 7;                  // lane within team
    float* __restrict__ ob = out + (size_t)b * (Nn * Cn) + c;
    const float* __restrict__ zrow = &S[Hn * Wn];

    for (int n = team; n < Nn; n += 32) {
        int4 q = BC[n];
        const float* __restrict__ r2 = (q.w > 0) ? &S[(q.w - 1) * Wn] : zrow;
        const float* __restrict__ r1 = (q.y > 0) ? &S[(q.y - 1) * Wn] : zrow;

        float s = 0.0f;
        for (int x = q.x + tl; x < q.z; x += 8)
            s += r2[x] - r1[x];

        // width-8 tree reduce (3 shuffles)
        s += __shfl_down_sync(0xFFFFFFFFu, s, 4, 8);
        s += __shfl_down_sync(0xFFFFFFFFu, s, 2, 8);
        s += __shfl_down_sync(0xFFFFFFFFu, s, 1, 8);

        if (tl == 0) {
            int dy = q.w - q.y;
            int dx = q.z - q.x;
            bool valid = (dy > 0) && (dx > 0);
            int  area  = max(dy * dx, 1);
            ob[(size_t)n * Cn] = valid ? s / (float)area : 0.0f;
        }
    }
}

extern "C" void kernel_launch(void* const* d_in, const int* in_sizes, int n_in,
                              void* d_out, int out_size)
{
    const float* fmap  = (const float*)d_in[0];   // [64,256,80,80]
    const float* boxes = (const float*)d_in[1];   // [64,100,4]
    float*       out   = (float*)d_out;           // [64,100,256]

    (void)in_sizes; (void)n_in; (void)out_size;

    roi_pool_v5_kernel<<<Bn * Cn, 256>>>(fmap, boxes, out);
}